// round 1
// baseline (speedup 1.0000x reference)
#include <cuda_runtime.h>
#include <math.h>

#define BB 8
#define LT 64
#define LV 16384
#define DD 256
#define EPSF 1e-6f

#define TNS 68   // tn shared stride ([k][t] layout, pad 64->68)
#define VSS 260  // v shared stride  ([r][k] layout, pad 256->260)
#define K2_SMEM ((DD*TNS + 64*VSS + 64 + 16*192) * 4)

__device__ float g_tn[BB*LT*DD];
__device__ float g_ES[(size_t)BB*LV*LT];
__device__ float g_den[BB*LT];
__device__ float g_num[BB*LT];
__device__ float g_zc[BB*LT];
__device__ float g_w[BB*LT];
__device__ unsigned g_mn[BB];
__device__ unsigned g_mx[BB];

__device__ __forceinline__ float fixf(float x) {
    if (isnan(x)) return 0.f;
    if (isinf(x)) return x > 0.f ? 3.402823466e38f : -3.402823466e38f;
    return x;
}

// ---------------- kernel 0: init accumulators ----------------
__global__ void k0_init() {
    int i = threadIdx.x;
    for (int j = i; j < BB*LT; j += blockDim.x) {
        g_den[j] = 0.f; g_num[j] = 0.f; g_zc[j] = 0.f;
    }
    if (i < BB) { g_mn[i] = 0x7F800000u; g_mx[i] = 0u; }
}

// ---------------- kernel 1: l2-normalize t ----------------
__global__ void k1_norm_t(const float* __restrict__ t) {
    int row = blockIdx.x;         // b*64 + t_idx, 0..511
    int tid = threadIdx.x;        // 0..255 = k
    float x = fixf(t[row*DD + tid]);
    float ss = x * x;
    #pragma unroll
    for (int o = 16; o >= 1; o >>= 1) ss += __shfl_xor_sync(0xffffffffu, ss, o);
    __shared__ float sh[8];
    if ((tid & 31) == 0) sh[tid >> 5] = ss;
    __syncthreads();
    float tot = 0.f;
    #pragma unroll
    for (int w = 0; w < 8; w++) tot += sh[w];
    float inv = 1.f / fmaxf(sqrtf(tot), EPSF);
    g_tn[row*DD + tid] = x * inv;
}

// ---------------- kernel 2: main fused S-GEMM + softmaxes ----------------
// Block tile: 64 v-rows x all 64 t x full k=256. 256 threads, each owns 4x4.
__global__ __launch_bounds__(256, 1) void k2_main(const float* __restrict__ v) {
    extern __shared__ float sm[];
    float* tn_s = sm;                 // [256][68]  (k-major, t inner)
    float* v_s  = sm + DD*TNS;        // [64][260]  (row-major, k inner)
    float* rn_s = v_s + 64*VSS;       // [64]
    float* red  = rn_s + 64;          // [16][192]

    int b    = blockIdx.y;
    int row0 = blockIdx.x * 64;
    int tid  = threadIdx.x;

    // load tn transposed into shared
    const float* tnb = g_tn + b*LT*DD;
    for (int idx = tid; idx < LT*DD; idx += 256) {
        int t = idx >> 8, k = idx & 255;
        tn_s[k*TNS + t] = tnb[t*DD + k];
    }
    // load v rows (nan_to_num)
    const float* vb = v + ((size_t)b*LV + row0)*DD;
    for (int idx = tid; idx < 64*DD; idx += 256) {
        int r = idx >> 8, k = idx & 255;
        v_s[r*VSS + k] = fixf(vb[r*DD + k]);
    }
    __syncthreads();

    // per-row inverse norm, folded with 1/TEMP
    {
        int r = tid & 63, q = tid >> 6;
        float s = 0.f;
        int k0 = q * 64;
        #pragma unroll 8
        for (int k = 0; k < 64; k++) { float x = v_s[r*VSS + k0 + k]; s += x*x; }
        red[tid] = s;
        __syncthreads();
        if (tid < 64) {
            float tot = red[tid] + red[tid+64] + red[tid+128] + red[tid+192];
            rn_s[tid] = 0.5f / fmaxf(sqrtf(tot), EPSF);   // 0.5 = 1/TEMP
        }
        __syncthreads();
    }

    int tx = tid & 15, ty = tid >> 4;   // tx -> t quad, ty -> row quad
    float acc[4][4];
    #pragma unroll
    for (int j = 0; j < 4; j++)
        #pragma unroll
        for (int i = 0; i < 4; i++) acc[j][i] = 0.f;

    #pragma unroll 4
    for (int k = 0; k < DD; k += 4) {
        float av[4][4];   // av[kk][i] = tn[k+kk][4tx+i]
        float bv[4][4];   // bv[j][kk] = v[4ty+j][k+kk]
        *(float4*)av[0] = *(const float4*)&tn_s[(k+0)*TNS + 4*tx];
        *(float4*)av[1] = *(const float4*)&tn_s[(k+1)*TNS + 4*tx];
        *(float4*)av[2] = *(const float4*)&tn_s[(k+2)*TNS + 4*tx];
        *(float4*)av[3] = *(const float4*)&tn_s[(k+3)*TNS + 4*tx];
        *(float4*)bv[0] = *(const float4*)&v_s[(4*ty+0)*VSS + k];
        *(float4*)bv[1] = *(const float4*)&v_s[(4*ty+1)*VSS + k];
        *(float4*)bv[2] = *(const float4*)&v_s[(4*ty+2)*VSS + k];
        *(float4*)bv[3] = *(const float4*)&v_s[(4*ty+3)*VSS + k];
        #pragma unroll
        for (int kk = 0; kk < 4; kk++)
            #pragma unroll
            for (int j = 0; j < 4; j++)
                #pragma unroll
                for (int i = 0; i < 4; i++)
                    acc[j][i] += bv[j][kk] * av[kk][i];
    }

    // epilogue: per-row softmax over t (64-wide) + accumulators
    float A_[4][4], ES_[4][4];
    #pragma unroll
    for (int j = 0; j < 4; j++) {
        float scale = rn_s[4*ty + j];
        float s0 = acc[j][0]*scale, s1 = acc[j][1]*scale,
              s2 = acc[j][2]*scale, s3 = acc[j][3]*scale;
        float m = fmaxf(fmaxf(s0, s1), fmaxf(s2, s3));
        #pragma unroll
        for (int o = 1; o < 16; o <<= 1) m = fmaxf(m, __shfl_xor_sync(0xffffffffu, m, o));
        float e0 = expf(s0 - m), e1 = expf(s1 - m), e2 = expf(s2 - m), e3 = expf(s3 - m);
        float z = e0 + e1 + e2 + e3;
        #pragma unroll
        for (int o = 1; o < 16; o <<= 1) z += __shfl_xor_sync(0xffffffffu, z, o);
        float invz = 1.f / z;
        float em = expf(m);
        A_[j][0] = e0*invz; A_[j][1] = e1*invz; A_[j][2] = e2*invz; A_[j][3] = e3*invz;
        ES_[j][0] = e0*em;  ES_[j][1] = e1*em;  ES_[j][2] = e2*em;  ES_[j][3] = e3*em;
    }

    // store exp(S) for pass 2
    #pragma unroll
    for (int j = 0; j < 4; j++) {
        float4 st = make_float4(ES_[j][0], ES_[j][1], ES_[j][2], ES_[j][3]);
        *(float4*)&g_ES[(((size_t)b*LV + row0 + 4*ty + j)*LT) + 4*tx] = st;
    }

    // per-t partial sums over this thread's 4 rows
    float dp[4] = {0,0,0,0}, np[4] = {0,0,0,0}, zp[4] = {0,0,0,0};
    #pragma unroll
    for (int j = 0; j < 4; j++)
        #pragma unroll
        for (int i = 0; i < 4; i++) {
            float a  = A_[j][i];
            float we = expf(a * 0.5f);   // exp(A_vt / TEMP), shift-free (a in (0,1])
            dp[i] += we;
            np[i] += we * a;
            zp[i] += ES_[j][i];          // sum_v exp(S), shift-free (|S|<=0.5)
        }
    #pragma unroll
    for (int i = 0; i < 4; i++) {
        red[ty*192 +       4*tx + i] = dp[i];
        red[ty*192 +  64 + 4*tx + i] = np[i];
        red[ty*192 + 128 + 4*tx + i] = zp[i];
    }
    __syncthreads();
    if (tid < 192) {
        float s = 0.f;
        #pragma unroll
        for (int y = 0; y < 16; y++) s += red[y*192 + tid];
        int which = tid >> 6, t = tid & 63;
        float* dst = (which == 0) ? g_den : ((which == 1) ? g_num : g_zc);
        atomicAdd(&dst[b*LT + t], s);
    }
}

// ---------------- kernel 3: text_score -> w = ts / Zc ----------------
__global__ void k3_ts() {
    int b = blockIdx.x, t = threadIdx.x;     // 64 threads
    int i = b*LT + t;
    float ts = g_num[i] / g_den[i];
    float s = ts;
    #pragma unroll
    for (int o = 16; o >= 1; o >>= 1) s += __shfl_xor_sync(0xffffffffu, s, o);
    __shared__ float sh[2];
    if ((t & 31) == 0) sh[t >> 5] = s;
    __syncthreads();
    float tot = sh[0] + sh[1];
    ts = ts / (tot + EPSF);
    g_w[i] = ts / g_zc[i];
}

// ---------------- kernel 4: scores = exp(S) . w, plus min/max ----------------
__global__ __launch_bounds__(256) void k4_score(float* __restrict__ out) {
    int b   = blockIdx.y;
    int tid = threadIdx.x;
    __shared__ float w_s[LT];
    __shared__ float sc_s[32];
    if (tid < LT) w_s[tid] = g_w[b*LT + tid];
    __syncthreads();
    int r  = blockIdx.x*32 + (tid >> 3);
    int l8 = tid & 7;
    const float* e = g_ES + ((size_t)b*LV + r)*LT + l8*8;
    float4 e0 = *(const float4*)e;
    float4 e1 = *(const float4*)(e + 4);
    const float* w = w_s + l8*8;
    float s = e0.x*w[0] + e0.y*w[1] + e0.z*w[2] + e0.w*w[3]
            + e1.x*w[4] + e1.y*w[5] + e1.z*w[6] + e1.w*w[7];
    s += __shfl_xor_sync(0xffffffffu, s, 1);
    s += __shfl_xor_sync(0xffffffffu, s, 2);
    s += __shfl_xor_sync(0xffffffffu, s, 4);
    if (l8 == 0) { out[(size_t)b*LV + r] = s; sc_s[tid >> 3] = s; }
    __syncthreads();
    if (tid == 0) {
        float mn = sc_s[0], mx = sc_s[0];
        #pragma unroll
        for (int i = 1; i < 32; i++) { mn = fminf(mn, sc_s[i]); mx = fmaxf(mx, sc_s[i]); }
        atomicMin(&g_mn[b], __float_as_uint(mn));   // scores > 0: uint order == float order
        atomicMax(&g_mx[b], __float_as_uint(mx));
    }
}

// ---------------- kernel 5: min-max rescale ----------------
__global__ void k5_final(float* __restrict__ out) {
    int idx = blockIdx.x*256 + threadIdx.x;   // 0..131071
    int b = idx >> 14;
    float mn = __uint_as_float(g_mn[b]);
    float mx = __uint_as_float(g_mx[b]);
    out[idx] = (out[idx] - mn) / (mx - mn + EPSF);
}

extern "C" void kernel_launch(void* const* d_in, const int* in_sizes, int n_in,
                              void* d_out, int out_size) {
    const float* t = (const float*)d_in[0];
    const float* v = (const float*)d_in[1];
    if (in_sizes[0] != BB*LT*DD) { const float* tmp = t; t = v; v = tmp; }

    cudaFuncSetAttribute(k2_main, cudaFuncAttributeMaxDynamicSharedMemorySize, K2_SMEM);

    k0_init<<<1, 256>>>();
    k1_norm_t<<<BB*LT, 256>>>(t);
    k2_main<<<dim3(LV/64, BB), 256, K2_SMEM>>>(v);
    k3_ts<<<BB, 64>>>();
    k4_score<<<dim3(LV/32, BB), 256>>>((float*)d_out);
    k5_final<<<(BB*LV)/256, 256>>>((float*)d_out);
}

// round 3
// speedup vs baseline: 1.3091x; 1.3091x over previous
#include <cuda_runtime.h>
#include <math.h>

#define BB 8
#define LT 64
#define LV 16384
#define DD 256
#define EPSF 1e-6f

#define TNS 258  // tn shared stride [t][k], pad 256->258 (stride % 32 == 2 -> conflict-free)
#define VSS 258  // v  shared stride [r][k]
#define K2_SMEM ((64*TNS + 64*VSS + 64 + 16*192) * 4)

typedef unsigned long long ull;

__device__ float g_tn[BB*LT*DD];
__device__ float g_ES[(size_t)BB*LV*LT];
__device__ float g_den[BB*LT];
__device__ float g_num[BB*LT];
__device__ float g_zc[BB*LT];
__device__ float g_w[BB*LT];
__device__ unsigned g_mn[BB];
__device__ unsigned g_mx[BB];

__device__ __forceinline__ float fixf(float x) {
    if (isnan(x)) return 0.f;
    if (isinf(x)) return x > 0.f ? 3.402823466e38f : -3.402823466e38f;
    return x;
}

#define FMA2(d, a, b) asm("fma.rn.f32x2 %0, %1, %2, %0;" : "+l"(d) : "l"(a), "l"(b))

__device__ __forceinline__ float h2sum(ull u) {
    float lo = __uint_as_float((unsigned)(u & 0xffffffffu));
    float hi = __uint_as_float((unsigned)(u >> 32));
    return lo + hi;
}

// ---------------- kernel 1: l2-normalize t (+ init accumulators from block 0) ----------------
__global__ void k1_norm_t(const float* __restrict__ t) {
    int row = blockIdx.x;         // b*64 + t_idx, 0..511
    int tid = threadIdx.x;        // 0..255 = k
    if (row == 0) {
        // FULL strided init (BB*LT = 512 > blockDim = 256!)
        for (int j = tid; j < BB*LT; j += 256) {
            g_den[j] = 0.f; g_num[j] = 0.f; g_zc[j] = 0.f;
        }
        if (tid < BB) { g_mn[tid] = 0x7F800000u; g_mx[tid] = 0u; }
    }
    float x = fixf(t[row*DD + tid]);
    float ss = x * x;
    #pragma unroll
    for (int o = 16; o >= 1; o >>= 1) ss += __shfl_xor_sync(0xffffffffu, ss, o);
    __shared__ float sh[8];
    if ((tid & 31) == 0) sh[tid >> 5] = ss;
    __syncthreads();
    float tot = 0.f;
    #pragma unroll
    for (int w = 0; w < 8; w++) tot += sh[w];
    float inv = 1.f / fmaxf(sqrtf(tot), EPSF);
    g_tn[row*DD + tid] = x * inv;
}

// ---------------- kernel 2: main fused S-GEMM (f32x2 packed) + softmaxes ----------------
// Block tile: 64 v-rows x 64 t x k=256. 256 threads, thread = (tx 0..15, ty 0..15),
// owns rows 4ty..4ty+3 and t-slots {tx, tx+16, tx+32, tx+48}. Acc packed over k-pairs.
__global__ __launch_bounds__(256, 1) void k2_main(const float* __restrict__ v) {
    extern __shared__ float sm[];
    float* tn_s = sm;                 // [64][258]  (t-major, k inner)
    float* v_s  = sm + 64*TNS;        // [64][258]
    float* rn_s = v_s + 64*VSS;       // [64]
    float* red  = rn_s + 64;          // [16][192]

    int b    = blockIdx.y;
    int row0 = blockIdx.x * 64;
    int tid  = threadIdx.x;

    // prologue: straight float2 copies (conflict-free)
    const float2* tnb = (const float2*)(g_tn + b*LT*DD);
    for (int idx = tid; idx < LT*DD/2; idx += 256) {
        int t = idx >> 7, j = idx & 127;
        *(float2*)&tn_s[t*TNS + 2*j] = tnb[t*128 + j];
    }
    const float2* vb = (const float2*)(v + ((size_t)b*LV + row0)*DD);
    for (int idx = tid; idx < 64*DD/2; idx += 256) {
        int r = idx >> 7, j = idx & 127;
        float2 x = vb[r*128 + j];
        x.x = fixf(x.x); x.y = fixf(x.y);
        *(float2*)&v_s[r*VSS + 2*j] = x;
    }
    __syncthreads();

    // per-row inverse norm, folded with 1/TEMP
    {
        int r = tid & 63, q = tid >> 6;
        float s = 0.f;
        int k0 = q * 64;
        #pragma unroll 8
        for (int k = 0; k < 64; k++) { float x = v_s[r*VSS + k0 + k]; s += x*x; }
        red[tid] = s;
        __syncthreads();
        if (tid < 64) {
            float tot = red[tid] + red[tid+64] + red[tid+128] + red[tid+192];
            rn_s[tid] = 0.5f / fmaxf(sqrtf(tot), EPSF);   // 0.5 = 1/TEMP
        }
        __syncthreads();
    }

    int tx = tid & 15, ty = tid >> 4;
    const float* a0p = &tn_s[ tx      *TNS];
    const float* a1p = &tn_s[(tx+16)*TNS];
    const float* a2p = &tn_s[(tx+32)*TNS];
    const float* a3p = &tn_s[(tx+48)*TNS];
    const float* b0p = &v_s[(4*ty+0)*VSS];
    const float* b1p = &v_s[(4*ty+1)*VSS];
    const float* b2p = &v_s[(4*ty+2)*VSS];
    const float* b3p = &v_s[(4*ty+3)*VSS];

    ull acc[4][4];   // [row j][t-slot q], packed pair over (k even, k odd)
    #pragma unroll
    for (int j = 0; j < 4; j++)
        #pragma unroll
        for (int q = 0; q < 4; q++) acc[j][q] = 0ull;

    #pragma unroll 4
    for (int kp = 0; kp < DD/2; kp++) {
        ull a[4], bb[4];
        a[0]  = *(const ull*)(a0p + 2*kp);
        a[1]  = *(const ull*)(a1p + 2*kp);
        a[2]  = *(const ull*)(a2p + 2*kp);
        a[3]  = *(const ull*)(a3p + 2*kp);
        bb[0] = *(const ull*)(b0p + 2*kp);
        bb[1] = *(const ull*)(b1p + 2*kp);
        bb[2] = *(const ull*)(b2p + 2*kp);
        bb[3] = *(const ull*)(b3p + 2*kp);
        #pragma unroll
        for (int j = 0; j < 4; j++)
            #pragma unroll
            for (int q = 0; q < 4; q++)
                FMA2(acc[j][q], bb[j], a[q]);
    }

    // epilogue: per-row softmax over t (16 lanes x 4 slots) + accumulators
    float A_[4][4], ES_[4][4];
    #pragma unroll
    for (int j = 0; j < 4; j++) {
        float scale = rn_s[4*ty + j];
        float s0 = h2sum(acc[j][0])*scale, s1 = h2sum(acc[j][1])*scale,
              s2 = h2sum(acc[j][2])*scale, s3 = h2sum(acc[j][3])*scale;
        float m = fmaxf(fmaxf(s0, s1), fmaxf(s2, s3));
        #pragma unroll
        for (int o = 1; o < 16; o <<= 1) m = fmaxf(m, __shfl_xor_sync(0xffffffffu, m, o));
        float e0 = __expf(s0 - m), e1 = __expf(s1 - m),
              e2 = __expf(s2 - m), e3 = __expf(s3 - m);
        float z = e0 + e1 + e2 + e3;
        #pragma unroll
        for (int o = 1; o < 16; o <<= 1) z += __shfl_xor_sync(0xffffffffu, z, o);
        float invz = 1.f / z;
        float em = __expf(m);
        A_[j][0] = e0*invz; A_[j][1] = e1*invz; A_[j][2] = e2*invz; A_[j][3] = e3*invz;
        ES_[j][0] = e0*em;  ES_[j][1] = e1*em;  ES_[j][2] = e2*em;  ES_[j][3] = e3*em;
    }

    // store exp(S) in permuted column order: col 4*tx+q holds t = tx+16q
    #pragma unroll
    for (int j = 0; j < 4; j++) {
        float4 st = make_float4(ES_[j][0], ES_[j][1], ES_[j][2], ES_[j][3]);
        *(float4*)&g_ES[(((size_t)b*LV + row0 + 4*ty + j)*LT) + 4*tx] = st;
    }

    // per-t partial sums over this thread's 4 rows
    float dp[4] = {0,0,0,0}, np[4] = {0,0,0,0}, zp[4] = {0,0,0,0};
    #pragma unroll
    for (int j = 0; j < 4; j++)
        #pragma unroll
        for (int q = 0; q < 4; q++) {
            float a  = A_[j][q];
            float we = __expf(a * 0.5f);   // exp(A_vt / TEMP), shift-free (a in (0,1])
            dp[q] += we;
            np[q] += we * a;
            zp[q] += ES_[j][q];            // sum_v exp(S), shift-free (|S|<=0.5)
        }
    #pragma unroll
    for (int q = 0; q < 4; q++) {
        int t = tx + 16*q;   // actual t index
        red[ty*192 +       t] = dp[q];
        red[ty*192 +  64 + t] = np[q];
        red[ty*192 + 128 + t] = zp[q];
    }
    __syncthreads();
    if (tid < 192) {
        float s = 0.f;
        #pragma unroll
        for (int y = 0; y < 16; y++) s += red[y*192 + tid];
        int which = tid >> 6, t = tid & 63;
        float* dst = (which == 0) ? g_den : ((which == 1) ? g_num : g_zc);
        atomicAdd(&dst[b*LT + t], s);
    }
}

// ---------------- kernel 3: text_score -> w = ts / Zc ----------------
__global__ void k3_ts() {
    int b = blockIdx.x, t = threadIdx.x;     // 64 threads
    int i = b*LT + t;
    float ts = g_num[i] / g_den[i];
    float s = ts;
    #pragma unroll
    for (int o = 16; o >= 1; o >>= 1) s += __shfl_xor_sync(0xffffffffu, s, o);
    __shared__ float sh[2];
    if ((t & 31) == 0) sh[t >> 5] = s;
    __syncthreads();
    float tot = sh[0] + sh[1];
    ts = ts / (tot + EPSF);
    g_w[i] = ts / g_zc[i];
}

// ---------------- kernel 4: scores = exp(S) . w (permuted cols), plus min/max ----------------
__global__ __launch_bounds__(256) void k4_score(float* __restrict__ out) {
    int b   = blockIdx.y;
    int tid = threadIdx.x;
    __shared__ float w_s[LT];
    __shared__ float sc_s[32];
    if (tid < LT) {
        // column i of g_ES holds t = (i>>2) + 16*(i&3)
        int t = (tid >> 2) + ((tid & 3) << 4);
        w_s[tid] = g_w[b*LT + t];
    }
    __syncthreads();
    int r  = blockIdx.x*32 + (tid >> 3);
    int l8 = tid & 7;
    const float* e = g_ES + ((size_t)b*LV + r)*LT + l8*8;
    float4 e0 = *(const float4*)e;
    float4 e1 = *(const float4*)(e + 4);
    const float* w = w_s + l8*8;
    float s = e0.x*w[0] + e0.y*w[1] + e0.z*w[2] + e0.w*w[3]
            + e1.x*w[4] + e1.y*w[5] + e1.z*w[6] + e1.w*w[7];
    s += __shfl_xor_sync(0xffffffffu, s, 1);
    s += __shfl_xor_sync(0xffffffffu, s, 2);
    s += __shfl_xor_sync(0xffffffffu, s, 4);
    if (l8 == 0) { out[(size_t)b*LV + r] = s; sc_s[tid >> 3] = s; }
    __syncthreads();
    if (tid == 0) {
        float mn = sc_s[0], mx = sc_s[0];
        #pragma unroll
        for (int i = 1; i < 32; i++) { mn = fminf(mn, sc_s[i]); mx = fmaxf(mx, sc_s[i]); }
        atomicMin(&g_mn[b], __float_as_uint(mn));   // scores > 0: uint order == float order
        atomicMax(&g_mx[b], __float_as_uint(mx));
    }
}

// ---------------- kernel 5: min-max rescale ----------------
__global__ void k5_final(float* __restrict__ out) {
    int idx = blockIdx.x*256 + threadIdx.x;   // 0..131071
    int b = idx >> 14;
    float mn = __uint_as_float(g_mn[b]);
    float mx = __uint_as_float(g_mx[b]);
    out[idx] = (out[idx] - mn) / (mx - mn + EPSF);
}

extern "C" void kernel_launch(void* const* d_in, const int* in_sizes, int n_in,
                              void* d_out, int out_size) {
    const float* t = (const float*)d_in[0];
    const float* v = (const float*)d_in[1];
    if (in_sizes[0] != BB*LT*DD) { const float* tmp = t; t = v; v = tmp; }

    cudaFuncSetAttribute(k2_main, cudaFuncAttributeMaxDynamicSharedMemorySize, K2_SMEM);

    k1_norm_t<<<BB*LT, 256>>>(t);
    k2_main<<<dim3(LV/64, BB), 256, K2_SMEM>>>(v);
    k3_ts<<<BB, 64>>>();
    k4_score<<<dim3(LV/32, BB), 256>>>((float*)d_out);
    k5_final<<<(BB*LV)/256, 256>>>((float*)d_out);
}

// round 5
// speedup vs baseline: 2.8446x; 2.1730x over previous
#include <cuda_runtime.h>
#include <cuda_bf16.h>
#include <math.h>
#include <cstdint>

#define BB 8
#define LT 64
#define LV 16384
#define DD 256
#define EPSF 1e-6f

typedef unsigned int uint32;

#define PK 264   // padded row stride in bf16 elems (528B; 528/4 % 32 == 4 -> ldmatrix conflict-free)

// smem byte offsets
#define SM_VH   0
#define SM_VL   67584
#define SM_TH   135168
#define SM_TL   168960
#define SM_RN   202752
#define SM_RED  203264
#define SM_TOTAL 209408

// ---------------- device globals ----------------
__device__ unsigned short g_th[BB*LT*DD];   // bf16 hi of normalized t
__device__ unsigned short g_tl[BB*LT*DD];   // bf16 lo
__device__ float g_ES[(size_t)BB*LV*LT];
__device__ float g_den[BB*LT];
__device__ float g_num[BB*LT];
__device__ float g_zc[BB*LT];
__device__ float g_w[BB*LT];
__device__ unsigned g_mn[BB];
__device__ unsigned g_mx[BB];

__device__ __forceinline__ float fixf(float x) {
    if (isnan(x)) return 0.f;
    return fminf(fmaxf(x, -3.402823466e38f), 3.402823466e38f);
}
__device__ __forceinline__ uint32 smem_u32(const void* p) {
    uint32 a;
    asm("{ .reg .u64 t; cvta.to.shared.u64 t, %1; cvt.u32.u64 %0, t; }" : "=r"(a) : "l"(p));
    return a;
}
__device__ __forceinline__ uint32 pack2(float a, float b) {
    __nv_bfloat162 h = __floats2bfloat162_rn(a, b);
    return *(uint32*)&h;
}

#define LDMX4(r, addr) \
    asm volatile("ldmatrix.sync.aligned.m8n8.x4.shared.b16 {%0,%1,%2,%3}, [%4];" \
        : "=r"((r)[0]), "=r"((r)[1]), "=r"((r)[2]), "=r"((r)[3]) : "r"(addr))

#define MMA(c, a, b0, b1) \
    asm volatile("mma.sync.aligned.m16n8k16.row.col.f32.bf16.bf16.f32 " \
        "{%0,%1,%2,%3},{%4,%5,%6,%7},{%8,%9},{%0,%1,%2,%3};" \
        : "+f"((c)[0]), "+f"((c)[1]), "+f"((c)[2]), "+f"((c)[3]) \
        : "r"((a)[0]), "r"((a)[1]), "r"((a)[2]), "r"((a)[3]), "r"(b0), "r"(b1))

// ---------------- kernel 1: normalize t -> bf16 hi/lo; init accumulators ----------------
__global__ void k1_norm_t(const float* __restrict__ t) {
    int row = blockIdx.x;         // 0..511
    int tid = threadIdx.x;        // 0..255 = k
    if (row == 0) {
        for (int j = tid; j < BB*LT; j += 256) {
            g_den[j] = 0.f; g_num[j] = 0.f; g_zc[j] = 0.f;
        }
        if (tid < BB) { g_mn[tid] = 0x7F800000u; g_mx[tid] = 0u; }
    }
    float x = fixf(t[row*DD + tid]);
    float ss = x * x;
    #pragma unroll
    for (int o = 16; o >= 1; o >>= 1) ss += __shfl_xor_sync(0xffffffffu, ss, o);
    __shared__ float sh[8];
    if ((tid & 31) == 0) sh[tid >> 5] = ss;
    __syncthreads();
    float tot = 0.f;
    #pragma unroll
    for (int w = 0; w < 8; w++) tot += sh[w];
    float xn = x / fmaxf(sqrtf(tot), EPSF);
    __nv_bfloat16 hi = __float2bfloat16(xn);
    __nv_bfloat16 lo = __float2bfloat16(xn - __bfloat162float(hi));
    g_th[row*DD + tid] = *(unsigned short*)&hi;
    g_tl[row*DD + tid] = *(unsigned short*)&lo;
}

// ---------------- kernel 2: HMMA bf16-split S-GEMM + fused softmaxes ----------------
// Block: 128 v-rows x 64 t x K=256. 8 warps; warp w owns rows 16w..16w+15, all 64 t.
__global__ __launch_bounds__(256, 1) void k2_main(const float* __restrict__ v) {
    extern __shared__ char smc[];
    uint32 smb = smem_u32(smc);
    int b    = blockIdx.y;
    int row0 = blockIdx.x * 128;
    int tid  = threadIdx.x;
    int lane = tid & 31, w = tid >> 5;
    float* rn_s = (float*)(smc + SM_RN);
    float* red  = (float*)(smc + SM_RED);

    // ---- prologue: copy t bf16 tiles into padded smem ----
    {
        const uint4* th4 = (const uint4*)(g_th + b*LT*DD);
        const uint4* tl4 = (const uint4*)(g_tl + b*LT*DD);
        for (int i = tid; i < LT*DD/8; i += 256) {
            int r = i >> 5, c = i & 31;
            uint32 off = (uint32)(r*PK + c*8) * 2;
            *(uint4*)(smc + SM_TH + off) = th4[i];
            *(uint4*)(smc + SM_TL + off) = tl4[i];
        }
    }
    // ---- prologue: split v into bf16 hi/lo + row norms ----
    {
        int row = tid >> 1, kb = (tid & 1) * 128;
        const float* vr = v + ((size_t)b*LV + row0 + row)*DD + kb;
        float ss = 0.f;
        #pragma unroll 4
        for (int c = 0; c < 16; c++) {
            float4 p0 = *(const float4*)(vr + c*8);
            float4 p1 = *(const float4*)(vr + c*8 + 4);
            float x[8];
            x[0]=fixf(p0.x); x[1]=fixf(p0.y); x[2]=fixf(p0.z); x[3]=fixf(p0.w);
            x[4]=fixf(p1.x); x[5]=fixf(p1.y); x[6]=fixf(p1.z); x[7]=fixf(p1.w);
            uint32 hi[4], lo[4];
            #pragma unroll
            for (int j = 0; j < 4; j++) {
                float a = x[2*j], bb2 = x[2*j+1];
                ss += a*a + bb2*bb2;
                __nv_bfloat16 ha = __float2bfloat16(a), hb = __float2bfloat16(bb2);
                float la = a - __bfloat162float(ha), lb = bb2 - __bfloat162float(hb);
                hi[j] = (uint32)(*(unsigned short*)&ha) | ((uint32)(*(unsigned short*)&hb) << 16);
                lo[j] = pack2(la, lb);
            }
            uint32 off = (uint32)(row*PK + kb + c*8) * 2;
            *(uint4*)(smc + SM_VH + off) = make_uint4(hi[0], hi[1], hi[2], hi[3]);
            *(uint4*)(smc + SM_VL + off) = make_uint4(lo[0], lo[1], lo[2], lo[3]);
        }
        ss += __shfl_xor_sync(0xffffffffu, ss, 1);
        if ((tid & 1) == 0) rn_s[row] = 0.5f / fmaxf(sqrtf(ss), EPSF);
    }
    __syncthreads();

    // ---- mainloop: 16 k-steps, 3 passes (vh.th + vl.th + vh.tl) ----
    float acc[8][4];
    #pragma unroll
    for (int nt = 0; nt < 8; nt++)
        #pragma unroll
        for (int j = 0; j < 4; j++) acc[nt][j] = 0.f;

    uint32 a_row = 16*w + (lane & 15);
    uint32 a_k8  = (lane >> 4) * 8;
    uint32 ah_addr = smb + SM_VH + (a_row*PK + a_k8) * 2;
    uint32 al_addr = smb + SM_VL + (a_row*PK + a_k8) * 2;
    uint32 b_row = (lane & 7) + ((lane >> 4) << 3);
    uint32 b_k8  = ((lane >> 3) & 1) * 8;
    uint32 b_off = (b_row*PK + b_k8) * 2;

    #pragma unroll 2
    for (int ks = 0; ks < 16; ks++) {
        uint32 ah[4], al[4];
        LDMX4(ah, ah_addr + ks*32);
        LDMX4(al, al_addr + ks*32);
        #pragma unroll
        for (int nc = 0; nc < 4; nc++) {
            uint32 boff = b_off + (uint32)nc*(16*PK*2) + ks*32;
            uint32 bh[4], bl[4];
            LDMX4(bh, smb + SM_TH + boff);
            LDMX4(bl, smb + SM_TL + boff);
            MMA(acc[2*nc],   ah, bh[0], bh[1]);
            MMA(acc[2*nc+1], ah, bh[2], bh[3]);
            MMA(acc[2*nc],   al, bh[0], bh[1]);
            MMA(acc[2*nc+1], al, bh[2], bh[3]);
            MMA(acc[2*nc],   ah, bl[0], bl[1]);
            MMA(acc[2*nc+1], ah, bl[2], bl[3]);
        }
    }

    // ---- epilogue: softmax over t per row, ES store, accumulators ----
    // c frag: row r1 = 16w + lane/4 -> c[0],c[1]; row r2 = r1+8 -> c[2],c[3];
    // col = nt*8 + (lane&3)*2 + e
    int r1 = 16*w + (lane >> 2);
    int r2 = r1 + 8;
    float sc1 = rn_s[r1], sc2 = rn_s[r2];

    float s1[16], s2[16];
    #pragma unroll
    for (int nt = 0; nt < 8; nt++) {
        s1[2*nt]   = acc[nt][0]*sc1; s1[2*nt+1] = acc[nt][1]*sc1;
        s2[2*nt]   = acc[nt][2]*sc2; s2[2*nt+1] = acc[nt][3]*sc2;
    }
    float m1 = s1[0], m2 = s2[0];
    #pragma unroll
    for (int i = 1; i < 16; i++) { m1 = fmaxf(m1, s1[i]); m2 = fmaxf(m2, s2[i]); }
    #pragma unroll
    for (int o = 1; o < 4; o <<= 1) {
        m1 = fmaxf(m1, __shfl_xor_sync(0xffffffffu, m1, o));
        m2 = fmaxf(m2, __shfl_xor_sync(0xffffffffu, m2, o));
    }
    float e1[16], e2[16];
    float z1 = 0.f, z2 = 0.f;
    #pragma unroll
    for (int i = 0; i < 16; i++) {
        e1[i] = __expf(s1[i] - m1); z1 += e1[i];
        e2[i] = __expf(s2[i] - m2); z2 += e2[i];
    }
    #pragma unroll
    for (int o = 1; o < 4; o <<= 1) {
        z1 += __shfl_xor_sync(0xffffffffu, z1, o);
        z2 += __shfl_xor_sync(0xffffffffu, z2, o);
    }
    float iz1 = 1.f / z1, iz2 = 1.f / z2;
    float em1 = __expf(m1), em2 = __expf(m2);

    float dp[16], np[16], zp[16];
    {
        float* es1p = &g_ES[((size_t)b*LV + row0 + r1)*LT + (lane & 3)*2];
        float* es2p = &g_ES[((size_t)b*LV + row0 + r2)*LT + (lane & 3)*2];
        #pragma unroll
        for (int nt = 0; nt < 8; nt++) {
            float es1a = e1[2*nt]*em1, es1b = e1[2*nt+1]*em1;   // exp(S) row1
            float es2a = e2[2*nt]*em2, es2b = e2[2*nt+1]*em2;
            *(float2*)(es1p + nt*8) = make_float2(es1a, es1b);
            *(float2*)(es2p + nt*8) = make_float2(es2a, es2b);
            float a1a = e1[2*nt]*iz1, a1b = e1[2*nt+1]*iz1;     // A_vt
            float a2a = e2[2*nt]*iz2, a2b = e2[2*nt+1]*iz2;
            float w1a = __expf(a1a*0.5f), w1b = __expf(a1b*0.5f);
            float w2a = __expf(a2a*0.5f), w2b = __expf(a2b*0.5f);
            dp[2*nt]   = w1a + w2a;         dp[2*nt+1] = w1b + w2b;
            np[2*nt]   = w1a*a1a + w2a*a2a; np[2*nt+1] = w1b*a1b + w2b*a2b;
            zp[2*nt]   = es1a + es2a;       zp[2*nt+1] = es1b + es2b;
        }
    }
    // reduce across the 8 row-groups in the warp (lane bits 2,3,4)
    #pragma unroll
    for (int o = 4; o <= 16; o <<= 1) {
        #pragma unroll
        for (int i = 0; i < 16; i++) {
            dp[i] += __shfl_xor_sync(0xffffffffu, dp[i], o);
            np[i] += __shfl_xor_sync(0xffffffffu, np[i], o);
            zp[i] += __shfl_xor_sync(0xffffffffu, zp[i], o);
        }
    }
    if (lane < 4) {
        #pragma unroll
        for (int nt = 0; nt < 8; nt++) {
            int col = nt*8 + lane*2;
            red[w*192 +       col] = dp[2*nt];  red[w*192 +       col+1] = dp[2*nt+1];
            red[w*192 +  64 + col] = np[2*nt];  red[w*192 +  64 + col+1] = np[2*nt+1];
            red[w*192 + 128 + col] = zp[2*nt];  red[w*192 + 128 + col+1] = zp[2*nt+1];
        }
    }
    __syncthreads();
    if (tid < 192) {
        float s = 0.f;
        #pragma unroll
        for (int y = 0; y < 8; y++) s += red[y*192 + tid];
        int which = tid >> 6, t = tid & 63;
        float* dst = (which == 0) ? g_den : ((which == 1) ? g_num : g_zc);
        atomicAdd(&dst[b*LT + t], s);
    }
}

// ---------------- kernel 3: text_score -> w = ts / Zc ----------------
__global__ void k3_ts() {
    int b = blockIdx.x, t = threadIdx.x;
    int i = b*LT + t;
    float ts = g_num[i] / g_den[i];
    float s = ts;
    #pragma unroll
    for (int o = 16; o >= 1; o >>= 1) s += __shfl_xor_sync(0xffffffffu, s, o);
    __shared__ float sh[2];
    if ((t & 31) == 0) sh[t >> 5] = s;
    __syncthreads();
    float tot = sh[0] + sh[1];
    ts = ts / (tot + EPSF);
    g_w[i] = ts / g_zc[i];
}

// ---------------- kernel 4: scores = exp(S) . w, plus min/max ----------------
__global__ __launch_bounds__(256) void k4_score(float* __restrict__ out) {
    int b   = blockIdx.y;
    int tid = threadIdx.x;
    __shared__ float w_s[LT];
    __shared__ float sc_s[32];
    if (tid < LT) w_s[tid] = g_w[b*LT + tid];
    __syncthreads();
    int r  = blockIdx.x*32 + (tid >> 3);
    int l8 = tid & 7;
    const float* e = g_ES + ((size_t)b*LV + r)*LT + l8*8;
    float4 e0 = *(const float4*)e;
    float4 e1 = *(const float4*)(e + 4);
    const float* w = w_s + l8*8;
    float s = e0.x*w[0] + e0.y*w[1] + e0.z*w[2] + e0.w*w[3]
            + e1.x*w[4] + e1.y*w[5] + e1.z*w[6] + e1.w*w[7];
    s += __shfl_xor_sync(0xffffffffu, s, 1);
    s += __shfl_xor_sync(0xffffffffu, s, 2);
    s += __shfl_xor_sync(0xffffffffu, s, 4);
    if (l8 == 0) { out[(size_t)b*LV + r] = s; sc_s[tid >> 3] = s; }
    __syncthreads();
    if (tid == 0) {
        float mn = sc_s[0], mx = sc_s[0];
        #pragma unroll
        for (int i = 1; i < 32; i++) { mn = fminf(mn, sc_s[i]); mx = fmaxf(mx, sc_s[i]); }
        atomicMin(&g_mn[b], __float_as_uint(mn));   // scores > 0: uint order == float order
        atomicMax(&g_mx[b], __float_as_uint(mx));
    }
}

// ---------------- kernel 5: min-max rescale ----------------
__global__ void k5_final(float* __restrict__ out) {
    int idx = blockIdx.x*256 + threadIdx.x;
    int b = idx >> 14;
    float mn = __uint_as_float(g_mn[b]);
    float mx = __uint_as_float(g_mx[b]);
    out[idx] = (out[idx] - mn) / (mx - mn + EPSF);
}

extern "C" void kernel_launch(void* const* d_in, const int* in_sizes, int n_in,
                              void* d_out, int out_size) {
    const float* t = (const float*)d_in[0];
    const float* v = (const float*)d_in[1];
    if (in_sizes[0] != BB*LT*DD) { const float* tmp = t; t = v; v = tmp; }

    cudaFuncSetAttribute(k2_main, cudaFuncAttributeMaxDynamicSharedMemorySize, SM_TOTAL);

    k1_norm_t<<<BB*LT, 256>>>(t);
    k2_main<<<dim3(LV/128, BB), 256, SM_TOTAL>>>(v);
    k3_ts<<<BB, 64>>>();
    k4_score<<<dim3(LV/32, BB), 256>>>((float*)d_out);
    k5_final<<<(BB*LV)/256, 256>>>((float*)d_out);
}